// round 1
// baseline (speedup 1.0000x reference)
#include <cuda_runtime.h>
#include <math.h>

#define E_NUM 100000
#define NN 5000

static const int E64 = E_NUM * 64;
static const int E128 = E_NUM * 128;
static const int N64 = NN * 64;

// ---------------- device scratch ----------------
__device__ float g_An[NN * 256];
__device__ float g_Bn[NN * 256];
__device__ float g_cut[E_NUM];
__device__ float g_h0[E_NUM * 256];
__device__ float g_h1[E_NUM * 256];
__device__ float g_lat[E_NUM * 256];
__device__ float g_wall[E_NUM * 320];
__device__ float g_fs[E_NUM * 64];
__device__ float g_fv[3 * E_NUM * 64];
__device__ float g_fs1[E_NUM * 64];
__device__ float g_fv1[3 * E_NUM * 64];
__device__ float g_ns[NN * 64];
__device__ float g_nv[3 * NN * 64];
__device__ float g_ns2[NN * 64];
__device__ float g_nv2[3 * NN * 64];
__device__ float g_ts[E_NUM * 128];
__device__ float g_tv[3 * E_NUM * 128];
__device__ float g_fs3[E_NUM * 128];
__device__ float g_fv3[3 * E_NUM * 128];
__device__ float g_fin[E_NUM * 128];
__device__ float g_sw1[128 * 128];
__device__ float g_vw1[128 * 128];

__device__ __forceinline__ float siluf(float x) { return x / (1.0f + expf(-x)); }

// ---------------- generic SGEMM: C(M,N) = [A1|A2](M,K1+K2) @ B(K1+K2,N) ----------------
// EPI: 0 none, 1 silu, 2 cut[m]*acc, 3 residual mix: C = c1*C + c2*cut[m]*acc
template <int EPI>
__global__ void __launch_bounds__(256) sgemm(
    const float* __restrict__ A1, int K1,
    const float* __restrict__ A2, int K2,
    const float* __restrict__ B, float* __restrict__ C,
    int M, int N,
    const float* __restrict__ cut, const float* __restrict__ res_p)
{
    const int K = K1 + K2;
    __shared__ float As[16][128];
    __shared__ float Bs[16][64];
    int tid = threadIdx.x;
    int tx = tid & 15, ty = tid >> 4;
    int m0 = blockIdx.x * 128;
    int n0 = blockIdx.y * 64;
    float acc[8][4];
#pragma unroll
    for (int i = 0; i < 8; i++)
#pragma unroll
        for (int j = 0; j < 4; j++) acc[i][j] = 0.0f;

    for (int k0 = 0; k0 < K; k0 += 16) {
        const float* A;
        int lda, kloc;
        if (k0 < K1) { A = A1; lda = K1; kloc = k0; }
        else { A = A2; lda = K2; kloc = k0 - K1; }
#pragma unroll
        for (int l = 0; l < 2; l++) {
            int idx = tid + l * 256;
            int row = idx >> 2;
            int kq = idx & 3;
            float4 v = make_float4(0.f, 0.f, 0.f, 0.f);
            int m = m0 + row;
            if (m < M) v = *reinterpret_cast<const float4*>(&A[(size_t)m * lda + kloc + kq * 4]);
            As[kq * 4 + 0][row] = v.x;
            As[kq * 4 + 1][row] = v.y;
            As[kq * 4 + 2][row] = v.z;
            As[kq * 4 + 3][row] = v.w;
        }
        {
            int row = tid >> 4;
            int col = (tid & 15) * 4;
            float4 v = *reinterpret_cast<const float4*>(&B[(size_t)(k0 + row) * N + n0 + col]);
            *reinterpret_cast<float4*>(&Bs[row][col]) = v;
        }
        __syncthreads();
#pragma unroll
        for (int kk = 0; kk < 16; kk++) {
            float a[8], b[4];
            float4 a0 = *reinterpret_cast<const float4*>(&As[kk][ty * 8]);
            float4 a1 = *reinterpret_cast<const float4*>(&As[kk][ty * 8 + 4]);
            a[0] = a0.x; a[1] = a0.y; a[2] = a0.z; a[3] = a0.w;
            a[4] = a1.x; a[5] = a1.y; a[6] = a1.z; a[7] = a1.w;
            float4 b0 = *reinterpret_cast<const float4*>(&Bs[kk][tx * 4]);
            b[0] = b0.x; b[1] = b0.y; b[2] = b0.z; b[3] = b0.w;
#pragma unroll
            for (int i = 0; i < 8; i++)
#pragma unroll
                for (int j = 0; j < 4; j++) acc[i][j] = fmaf(a[i], b[j], acc[i][j]);
        }
        __syncthreads();
    }

    float c1 = 0.f, c2 = 0.f;
    if (EPI == 3) {
        float av = 1.0f / (1.0f + expf(-res_p[1]));
        c1 = sqrtf(1.0f - av);
        c2 = sqrtf(av);
    }
#pragma unroll
    for (int i = 0; i < 8; i++) {
        int m = m0 + ty * 8 + i;
        if (m >= M) continue;
        float rs = (EPI == 2 || EPI == 3) ? cut[m] : 0.0f;
#pragma unroll
        for (int j = 0; j < 4; j++) {
            int n = n0 + tx * 4 + j;
            float v = acc[i][j];
            if (EPI == 1) v = siluf(v);
            else if (EPI == 2) v = rs * v;
            else if (EPI == 3) v = c1 * C[(size_t)m * N + n] + c2 * rs * v;
            C[(size_t)m * N + n] = v;
        }
    }
}

// ---------------- first layer: h0 = silu(An[c] + Bn[n] + radial @ w0r), cut ----------------
__global__ void k_first(const float* __restrict__ radial, const float* __restrict__ elen,
                        const int* __restrict__ eidx, const float* __restrict__ w0r)
{
    int e = blockIdx.x;
    int t = threadIdx.x;  // 256
    __shared__ float r[8];
    if (t < 8) r[t] = radial[e * 8 + t];
    if (t == 0) {
        float x = elen[e] * 0.2f;  // / R_MAX
        float x2 = x * x;
        float x6 = x2 * x2 * x2;
        float o = 1.0f - 28.0f * x6 + 48.0f * x6 * x - 21.0f * x6 * x2;
        g_cut[e] = (x < 1.0f) ? o : 0.0f;
    }
    __syncthreads();
    int c = eidx[e];
    int n = eidx[E_NUM + e];
    float acc = g_An[c * 256 + t] + g_Bn[n * 256 + t];
#pragma unroll
    for (int j = 0; j < 8; j++) acc = fmaf(r[j], w0r[j * 256 + t], acc);
    g_h0[(size_t)e * 256 + t] = siluf(acc);
}

// ---------------- zero ns/nv ----------------
__global__ void k_zero()
{
    int i = blockIdx.x * 256 + threadIdx.x;
    if (i < NN * 64) {
        g_ns[i] = 0.f;
        g_nv[i] = 0.f;
        g_nv[NN * 64 + i] = 0.f;
        g_nv[2 * NN * 64 + i] = 0.f;
    }
}

// ---------------- env stage 0: fs/fv from w_feat*gate, atomics from w_env ----------------
__global__ void k_env0(const float* __restrict__ ang, const int* __restrict__ center)
{
    int idx = blockIdx.x * blockDim.x + threadIdx.x;
    if (idx >= E_NUM * 64) return;
    int e = idx >> 6, u = idx & 63;
    float4 sh = *reinterpret_cast<const float4*>(&ang[e * 4]);
    const float* w = &g_wall[(size_t)e * 320];
    float gate = w[128 + u];
    float wf0 = w[192 + 2 * u], wf1 = w[193 + 2 * u];
    g_fs[idx] = wf0 * sh.x * gate;
    g_fv[idx] = wf1 * sh.y * gate;
    g_fv[E_NUM * 64 + idx] = wf1 * sh.z * gate;
    g_fv[2 * E_NUM * 64 + idx] = wf1 * sh.w * gate;
    float we0 = w[2 * u], we1 = w[2 * u + 1];
    int c = center[e];
    atomicAdd(&g_ns[c * 64 + u], we0 * sh.x);
    atomicAdd(&g_nv[c * 64 + u], we1 * sh.y);
    atomicAdd(&g_nv[NN * 64 + c * 64 + u], we1 * sh.z);
    atomicAdd(&g_nv[2 * NN * 64 + c * 64 + u], we1 * sh.w);
}

// ---------------- env stage 1: fs1/fv1 *= gate, atomics from w_env ----------------
__global__ void k_env1(const float* __restrict__ ang, const int* __restrict__ center)
{
    int idx = blockIdx.x * blockDim.x + threadIdx.x;
    if (idx >= E_NUM * 64) return;
    int e = idx >> 6, u = idx & 63;
    float4 sh = *reinterpret_cast<const float4*>(&ang[e * 4]);
    const float* w = &g_wall[(size_t)e * 192];
    float gate = w[128 + u];
    g_fs1[idx] *= gate;
    g_fv1[idx] *= gate;
    g_fv1[E_NUM * 64 + idx] *= gate;
    g_fv1[2 * E_NUM * 64 + idx] *= gate;
    float we0 = w[2 * u], we1 = w[2 * u + 1];
    int c = center[e];
    atomicAdd(&g_ns[c * 64 + u], we0 * sh.x);
    atomicAdd(&g_nv[c * 64 + u], we1 * sh.y);
    atomicAdd(&g_nv[NN * 64 + c * 64 + u], we1 * sh.z);
    atomicAdd(&g_nv[2 * NN * 64 + c * 64 + u], we1 * sh.w);
}

// ---------------- per-node linear (with /AVG_NEIGH folded in) ----------------
__global__ void k_nodelin(const float* __restrict__ W)
{
    int nn = blockIdx.x;
    int t = threadIdx.x;  // 256
    __shared__ float sin_[256];
    int ch = t >> 6, v = t & 63;
    float val = (ch == 0) ? g_ns[nn * 64 + v] : g_nv[(ch - 1) * NN * 64 + nn * 64 + v];
    sin_[t] = val * 0.05f;  // / AVG_NEIGH
    __syncthreads();
    const float* Wm = W + (ch == 0 ? 0 : 64 * 64);
    float acc = 0.f;
#pragma unroll
    for (int u = 0; u < 64; u++) acc = fmaf(sin_[ch * 64 + u], Wm[u * 64 + v], acc);
    if (ch == 0) g_ns2[nn * 64 + v] = acc;
    else g_nv2[(ch - 1) * NN * 64 + nn * 64 + v] = acc;
}

// ---------------- tensor product uuu: build ts (E,128) and tv (3,E,128) ----------------
__global__ void k_tp(const float* __restrict__ fs, const float* __restrict__ fv,
                     const int* __restrict__ center)
{
    int idx = blockIdx.x * blockDim.x + threadIdx.x;
    if (idx >= E_NUM * 64) return;
    int e = idx >> 6, u = idx & 63;
    int c = center[e];
    float s2 = g_ns2[c * 64 + u];
    float vx = g_nv2[c * 64 + u];
    float vy = g_nv2[NN * 64 + c * 64 + u];
    float vz = g_nv2[2 * NN * 64 + c * 64 + u];
    float f = fs[idx];
    float fx = fv[idx];
    float fy = fv[E_NUM * 64 + idx];
    float fz = fv[2 * E_NUM * 64 + idx];
    const float IS3 = 0.57735026918962576f;
    size_t b = (size_t)e * 128 + u;
    g_ts[b] = f * s2;
    g_ts[b + 64] = (fx * vx + fy * vy + fz * vz) * IS3;
    g_tv[b] = f * vx * IS3;
    g_tv[b + 64] = fx * s2 * IS3;
    g_tv[(size_t)E_NUM * 128 + b] = f * vy * IS3;
    g_tv[(size_t)E_NUM * 128 + b + 64] = fy * s2 * IS3;
    g_tv[(size_t)2 * E_NUM * 128 + b] = f * vz * IS3;
    g_tv[(size_t)2 * E_NUM * 128 + b + 64] = fz * s2 * IS3;
}

// ---------------- repack lin1 weights (2,2,64,64) -> (128,128) ----------------
__global__ void k_prep(const float* __restrict__ sw, const float* __restrict__ vw)
{
    int idx = blockIdx.x * 256 + threadIdx.x;
    if (idx >= 2 * 2 * 64 * 64) return;
    int v = idx & 63;
    int u = (idx >> 6) & 63;
    int o = (idx >> 12) & 1;
    int i = (idx >> 13) & 1;
    int dst = (i * 64 + u) * 128 + o * 64 + v;
    g_sw1[dst] = sw[idx];
    g_vw1[dst] = vw[idx];
}

// ---------------- final output assembly ----------------
__global__ void k_out(float* __restrict__ out)
{
    int idx = blockIdx.x * blockDim.x + threadIdx.x;
    if (idx >= E_NUM * 128) return;
    int e = idx >> 7, q = idx & 127;
    out[(size_t)e * 512 + q] = g_fs3[idx] * g_fin[idx];
    float a = g_fv3[idx];
    float b = g_fv3[E_NUM * 128 + idx];
    float c = g_fv3[2 * E_NUM * 128 + idx];
    size_t base = (size_t)e * 512 + 128 + (size_t)q * 3;
    out[base] = a;
    out[base + 1] = b;
    out[base + 2] = c;
}

// ---------------- host launch ----------------
template <typename T>
static float* symaddr(const T& sym)
{
    void* p = nullptr;
    cudaGetSymbolAddress(&p, sym);
    return (float*)p;
}

extern "C" void kernel_launch(void* const* d_in, const int* in_sizes, int n_in,
                              void* d_out, int out_size)
{
    const float* node_attrs = (const float*)d_in[0];
    const float* radial = (const float*)d_in[1];
    const float* ang = (const float*)d_in[2];
    const float* elen = (const float*)d_in[3];
    const int* eidx = (const int*)d_in[4];
    const float* tb_w0 = (const float*)d_in[5];
    const float* tb_w1 = (const float*)d_in[6];
    const float* tb_w2 = (const float*)d_in[7];
    const float* lat1_w0 = (const float*)d_in[8];
    const float* lat1_w1 = (const float*)d_in[9];
    const float* env0_w = (const float*)d_in[10];
    const float* env1_w = (const float*)d_in[11];
    const float* envlin0 = (const float*)d_in[12];
    const float* envlin1 = (const float*)d_in[13];
    const float* lin0_sw = (const float*)d_in[14];
    const float* lin0_vw = (const float*)d_in[15];
    const float* lin1_sw = (const float*)d_in[16];
    const float* lin1_vw = (const float*)d_in[17];
    const float* fin_w0 = (const float*)d_in[18];
    const float* fin_w1 = (const float*)d_in[19];
    const float* res_p = (const float*)d_in[20];
    float* out = (float*)d_out;

    float* An = symaddr(g_An);
    float* Bn = symaddr(g_Bn);
    float* cut = symaddr(g_cut);
    float* h0 = symaddr(g_h0);
    float* h1 = symaddr(g_h1);
    float* lat = symaddr(g_lat);
    float* wall = symaddr(g_wall);
    float* fs = symaddr(g_fs);
    float* fv = symaddr(g_fv);
    float* fs1 = symaddr(g_fs1);
    float* fv1 = symaddr(g_fv1);
    float* ts = symaddr(g_ts);
    float* tv = symaddr(g_tv);
    float* fs3 = symaddr(g_fs3);
    float* fv3 = symaddr(g_fv3);
    float* fin = symaddr(g_fin);
    float* sw1 = symaddr(g_sw1);
    float* vw1 = symaddr(g_vw1);

    (void)in_sizes; (void)n_in; (void)out_size;

    auto grid = [](int M, int N) { return dim3((M + 127) / 128, N / 64); };
    const int EW = (E_NUM * 64 + 255) / 256;
    const int ZB = (NN * 64 + 255) / 256;

    // node precompute: An = node @ tb_w0[0:64], Bn = node @ tb_w0[64:128]
    sgemm<0><<<grid(NN, 256), 256>>>(node_attrs, 64, nullptr, 0, tb_w0, An, NN, 256, nullptr, nullptr);
    sgemm<0><<<grid(NN, 256), 256>>>(node_attrs, 64, nullptr, 0, tb_w0 + 64 * 256, Bn, NN, 256, nullptr, nullptr);

    // first layer + cut
    k_first<<<E_NUM, 256>>>(radial, elen, eidx, tb_w0 + 128 * 256);

    // tb MLP
    sgemm<1><<<grid(E_NUM, 256), 256>>>(h0, 256, nullptr, 0, tb_w1, h1, E_NUM, 256, nullptr, nullptr);
    sgemm<2><<<grid(E_NUM, 256), 256>>>(h1, 256, nullptr, 0, tb_w2, lat, E_NUM, 256, cut, nullptr);

    // env0
    sgemm<0><<<grid(E_NUM, 320), 256>>>(lat, 256, nullptr, 0, env0_w, wall, E_NUM, 320, nullptr, nullptr);
    k_zero<<<ZB, 256>>>();
    k_env0<<<EW, 256>>>(ang, eidx);
    k_nodelin<<<NN, 256>>>(envlin0);
    k_tp<<<EW, 256>>>(fs, fv, eidx);

    // lin0
    sgemm<0><<<grid(E_NUM, 64), 256>>>(ts, 128, nullptr, 0, lin0_sw, fs1, E_NUM, 64, nullptr, nullptr);
    for (int c = 0; c < 3; c++)
        sgemm<0><<<grid(E_NUM, 64), 256>>>(tv + (size_t)c * E128, 128, nullptr, 0, lin0_vw,
                                           fv1 + (size_t)c * E64, E_NUM, 64, nullptr, nullptr);

    // lat1 MLP + residual
    sgemm<1><<<grid(E_NUM, 256), 256>>>(lat, 256, ts, 128, lat1_w0, h1, E_NUM, 256, nullptr, nullptr);
    sgemm<3><<<grid(E_NUM, 256), 256>>>(h1, 256, nullptr, 0, lat1_w1, lat, E_NUM, 256, cut, res_p);

    // env1
    sgemm<0><<<grid(E_NUM, 192), 256>>>(lat, 256, nullptr, 0, env1_w, wall, E_NUM, 192, nullptr, nullptr);
    k_zero<<<ZB, 256>>>();
    k_env1<<<EW, 256>>>(ang, eidx);
    k_nodelin<<<NN, 256>>>(envlin1);
    k_tp<<<EW, 256>>>(fs1, fv1, eidx);

    // lin1
    k_prep<<<(2 * 2 * 64 * 64 + 255) / 256, 256>>>(lin1_sw, lin1_vw);
    sgemm<0><<<grid(E_NUM, 128), 256>>>(ts, 128, nullptr, 0, sw1, fs3, E_NUM, 128, nullptr, nullptr);
    for (int c = 0; c < 3; c++)
        sgemm<0><<<grid(E_NUM, 128), 256>>>(tv + (size_t)c * E128, 128, nullptr, 0, vw1,
                                            fv3 + (size_t)c * E128, E_NUM, 128, nullptr, nullptr);

    // fin MLP
    sgemm<1><<<grid(E_NUM, 256), 256>>>(lat, 256, ts, 128, fin_w0, h1, E_NUM, 256, nullptr, nullptr);
    sgemm<0><<<grid(E_NUM, 128), 256>>>(h1, 256, nullptr, 0, fin_w1, fin, E_NUM, 128, nullptr, nullptr);

    // output
    k_out<<<(E_NUM * 128 + 255) / 256, 256>>>(out);
}

// round 3
// speedup vs baseline: 1.3205x; 1.3205x over previous
#include <cuda_runtime.h>
#include <math.h>

#define E_NUM 100000
#define NN 5000

// ---------------- device scratch ----------------
__device__ __align__(16) float g_An[NN * 256];
__device__ __align__(16) float g_Bn[NN * 256];
__device__ __align__(16) float g_cut[E_NUM];
__device__ __align__(16) float g_h0[E_NUM * 256];
__device__ __align__(16) float g_h1[E_NUM * 256];
__device__ __align__(16) float g_lat[E_NUM * 256];
__device__ __align__(16) float g_wall[E_NUM * 320];
__device__ __align__(16) float g_fs[E_NUM * 64];
__device__ __align__(16) float g_fv[3 * E_NUM * 64];
__device__ __align__(16) float g_fs1[E_NUM * 64];
__device__ __align__(16) float g_fv1[3 * E_NUM * 64];
__device__ __align__(16) float g_ns[NN * 64];
__device__ __align__(16) float g_nv[3 * NN * 64];
__device__ __align__(16) float g_ns2[NN * 64];
__device__ __align__(16) float g_nv2[3 * NN * 64];
__device__ __align__(16) float g_ts[E_NUM * 128];
__device__ __align__(16) float g_tv[3 * E_NUM * 128];
__device__ __align__(16) float g_fs3[E_NUM * 128];
__device__ __align__(16) float g_fv3[3 * E_NUM * 128];
__device__ __align__(16) float g_fin[E_NUM * 128];
__device__ __align__(16) float g_sw1[128 * 128];
__device__ __align__(16) float g_vw1[128 * 128];

__device__ __forceinline__ float siluf(float x) { return x / (1.0f + expf(-x)); }

__device__ __forceinline__ unsigned f2tf(float x)
{
    unsigned r;
    asm("cvt.rna.tf32.f32 %0, %1;" : "=r"(r) : "f"(x));
    return r;
}

// 3xTF32 split: x = hi + lo (both exactly representable in tf32)
__device__ __forceinline__ void tfsplit(float x, unsigned& hi, unsigned& lo)
{
    hi = f2tf(x);
    lo = f2tf(x - __uint_as_float(hi));
}

__device__ __forceinline__ void cp16(unsigned d, const void* s, int sz)
{
    asm volatile("cp.async.cg.shared.global [%0], [%1], 16, %2;\n" :: "r"(d), "l"(s), "r"(sz));
}
__device__ __forceinline__ void cp_commit() { asm volatile("cp.async.commit_group;\n"); }
__device__ __forceinline__ void cp_wait1() { asm volatile("cp.async.wait_group 1;\n"); }

#define MMA_TF32(ACC, A0, A1, A2, A3, B0, B1)                                     \
    asm volatile(                                                                 \
        "mma.sync.aligned.m16n8k8.row.col.f32.tf32.tf32.f32 "                     \
        "{%0,%1,%2,%3},{%4,%5,%6,%7},{%8,%9},{%0,%1,%2,%3};"                      \
        : "+f"((ACC)[0]), "+f"((ACC)[1]), "+f"((ACC)[2]), "+f"((ACC)[3])          \
        : "r"(A0), "r"(A1), "r"(A2), "r"(A3), "r"(B0), "r"(B1))

// ============ 3xTF32 tensor-core GEMM: C(M,N) = [A1|A2](M,K1+K2) @ B(K1+K2,N) ============
// EPI: 0 none, 1 silu, 2 cut[m]*acc, 3 residual: C = c1*C + c2*cut[m]*acc
template <int BN, int EPI>
__global__ void __launch_bounds__(256) gemm_tc(
    const float* __restrict__ A1, int K1,
    const float* __restrict__ A2, int K2,
    const float* __restrict__ B, float* __restrict__ C,
    int M, int N,
    const float* __restrict__ cut, const float* __restrict__ res_p)
{
    constexpr int BM = 128, BK = 32;
    constexpr int WARPS_M = (BN == 128) ? 2 : 4;
    constexpr int WM = BM / WARPS_M;       // 64 or 32
    constexpr int WN = BN / (8 / WARPS_M); // 32
    constexpr int MT = WM / 16;            // 4 or 2
    constexpr int NT = WN / 8;             // 4
    constexpr int ASTR = 36;
    constexpr int BSTR = BN + 8;

    extern __shared__ float sm[];
    float* As = sm;                  // [2][BM][ASTR]
    float* Bs = sm + 2 * BM * ASTR;  // [2][BK][BSTR]
    unsigned asb = (unsigned)__cvta_generic_to_shared(As);
    unsigned bsb = (unsigned)__cvta_generic_to_shared(Bs);

    const int tid = threadIdx.x;
    const int lane = tid & 31;
    const int warp = tid >> 5;
    const int g = lane >> 2;
    const int kq = lane & 3;
    const int wm = warp & (WARPS_M - 1);
    const int wn = warp / WARPS_M;
    const int m0 = blockIdx.x * BM;
    const int n0 = blockIdx.y * BN;
    const int K = K1 + K2;
    const int T = K / BK;

    float acc[MT][NT][4];
#pragma unroll
    for (int i = 0; i < MT; i++)
#pragma unroll
        for (int j = 0; j < NT; j++)
#pragma unroll
            for (int q = 0; q < 4; q++) acc[i][j][q] = 0.0f;

    auto loadA = [&](int kt, int buf) {
        int k0 = kt * BK;
        const float* A; int lda, kl;
        if (k0 < K1) { A = A1; lda = K1; kl = k0; }
        else { A = A2; lda = K2; kl = k0 - K1; }
        int c = (tid & 7) * 4;
        int mb = tid >> 3;
#pragma unroll
        for (int p = 0; p < 4; p++) {
            int m = mb + p * 32;
            int gm = m0 + m;
            unsigned dst = asb + (unsigned)(((buf * BM + m) * ASTR + c) * 4);
            const float* src = A + (size_t)gm * lda + kl + c;
            cp16(dst, src, (gm < M) ? 16 : 0);
        }
    };
    auto loadB = [&](int kt, int buf) {
        int k0 = kt * BK;
        constexpr int F4 = BN / 4;
        constexpr int RPP = 256 / F4;
        int c = (tid & (F4 - 1)) * 4;
        int rb = tid / F4;
#pragma unroll
        for (int p = 0; p < BK / RPP; p++) {
            int r = rb + p * RPP;
            unsigned dst = bsb + (unsigned)(((buf * BK + r) * BSTR + c) * 4);
            const float* src = B + (size_t)(k0 + r) * N + n0 + c;
            cp16(dst, src, 16);
        }
    };
    auto compute = [&](int buf) {
#pragma unroll
        for (int ks = 0; ks < BK / 8; ks++) {
            unsigned ah[MT][4], al[MT][4], bh[NT][2], bl[NT][2];
#pragma unroll
            for (int mt = 0; mt < MT; mt++) {
                int r = wm * WM + mt * 16 + g;
                const float* ap = &As[(buf * BM + r) * ASTR + ks * 8 + kq];
                tfsplit(ap[0], ah[mt][0], al[mt][0]);
                tfsplit(ap[8 * ASTR], ah[mt][1], al[mt][1]);
                tfsplit(ap[4], ah[mt][2], al[mt][2]);
                tfsplit(ap[8 * ASTR + 4], ah[mt][3], al[mt][3]);
            }
#pragma unroll
            for (int nt = 0; nt < NT; nt++) {
                int n = wn * WN + nt * 8 + g;
                const float* bp = &Bs[(buf * BK + ks * 8 + kq) * BSTR + n];
                tfsplit(bp[0], bh[nt][0], bl[nt][0]);
                tfsplit(bp[4 * BSTR], bh[nt][1], bl[nt][1]);
            }
            // 3xTF32: lo*hi + hi*lo + hi*hi (drop lo*lo)
#pragma unroll
            for (int mt = 0; mt < MT; mt++)
#pragma unroll
                for (int nt = 0; nt < NT; nt++) {
                    MMA_TF32(acc[mt][nt], al[mt][0], al[mt][1], al[mt][2], al[mt][3],
                             bh[nt][0], bh[nt][1]);
                    MMA_TF32(acc[mt][nt], ah[mt][0], ah[mt][1], ah[mt][2], ah[mt][3],
                             bl[nt][0], bl[nt][1]);
                    MMA_TF32(acc[mt][nt], ah[mt][0], ah[mt][1], ah[mt][2], ah[mt][3],
                             bh[nt][0], bh[nt][1]);
                }
        }
    };

    loadA(0, 0); loadB(0, 0); cp_commit();
    for (int t = 0; t < T; t++) {
        if (t + 1 < T) { loadA(t + 1, (t + 1) & 1); loadB(t + 1, (t + 1) & 1); }
        cp_commit();
        cp_wait1();
        __syncthreads();
        compute(t & 1);
        __syncthreads();
    }

    // ---- epilogue ----
    float rc1 = 0.f, rc2 = 0.f;
    if (EPI == 3) {
        float av = 1.0f / (1.0f + expf(-res_p[1]));
        rc1 = sqrtf(1.0f - av);
        rc2 = sqrtf(av);
    }
#pragma unroll
    for (int mt = 0; mt < MT; mt++) {
#pragma unroll
        for (int h = 0; h < 2; h++) {
            int row = m0 + wm * WM + mt * 16 + g + h * 8;
            if (row >= M) continue;
            float rs = (EPI == 2 || EPI == 3) ? cut[row] : 0.0f;
#pragma unroll
            for (int nt = 0; nt < NT; nt++) {
                int col = n0 + wn * WN + nt * 8 + kq * 2;
                float v0 = acc[mt][nt][2 * h];
                float v1 = acc[mt][nt][2 * h + 1];
                if (EPI == 1) { v0 = siluf(v0); v1 = siluf(v1); }
                else if (EPI == 2) { v0 *= rs; v1 *= rs; }
                else if (EPI == 3) {
                    float2 o = *reinterpret_cast<const float2*>(&C[(size_t)row * N + col]);
                    v0 = rc1 * o.x + rc2 * rs * v0;
                    v1 = rc1 * o.y + rc2 * rs * v1;
                }
                float2 w = make_float2(v0, v1);
                *reinterpret_cast<float2*>(&C[(size_t)row * N + col]) = w;
            }
        }
    }
}

// ---------------- first layer ----------------
__global__ void k_first(const float* __restrict__ radial, const float* __restrict__ elen,
                        const int* __restrict__ eidx, const float* __restrict__ w0r)
{
    int e = blockIdx.x;
    int t = threadIdx.x;
    __shared__ float r[8];
    if (t < 8) r[t] = radial[e * 8 + t];
    if (t == 0) {
        float x = elen[e] * 0.2f;
        float x2 = x * x;
        float x6 = x2 * x2 * x2;
        float o = 1.0f - 28.0f * x6 + 48.0f * x6 * x - 21.0f * x6 * x2;
        g_cut[e] = (x < 1.0f) ? o : 0.0f;
    }
    __syncthreads();
    int c = eidx[e];
    int n = eidx[E_NUM + e];
    float acc = g_An[c * 256 + t] + g_Bn[n * 256 + t];
#pragma unroll
    for (int j = 0; j < 8; j++) acc = fmaf(r[j], w0r[j * 256 + t], acc);
    g_h0[(size_t)e * 256 + t] = siluf(acc);
}

__global__ void k_zero()
{
    int i = blockIdx.x * 256 + threadIdx.x;
    if (i < NN * 64) {
        g_ns[i] = 0.f;
        g_nv[i] = 0.f;
        g_nv[NN * 64 + i] = 0.f;
        g_nv[2 * NN * 64 + i] = 0.f;
    }
}

__global__ void k_env0(const float* __restrict__ ang, const int* __restrict__ center)
{
    int idx = blockIdx.x * blockDim.x + threadIdx.x;
    if (idx >= E_NUM * 64) return;
    int e = idx >> 6, u = idx & 63;
    float4 sh = *reinterpret_cast<const float4*>(&ang[e * 4]);
    const float* w = &g_wall[(size_t)e * 320];
    float gate = w[128 + u];
    float wf0 = w[192 + 2 * u], wf1 = w[193 + 2 * u];
    g_fs[idx] = wf0 * sh.x * gate;
    g_fv[idx] = wf1 * sh.y * gate;
    g_fv[E_NUM * 64 + idx] = wf1 * sh.z * gate;
    g_fv[2 * E_NUM * 64 + idx] = wf1 * sh.w * gate;
    float we0 = w[2 * u], we1 = w[2 * u + 1];
    int c = center[e];
    atomicAdd(&g_ns[c * 64 + u], we0 * sh.x);
    atomicAdd(&g_nv[c * 64 + u], we1 * sh.y);
    atomicAdd(&g_nv[NN * 64 + c * 64 + u], we1 * sh.z);
    atomicAdd(&g_nv[2 * NN * 64 + c * 64 + u], we1 * sh.w);
}

__global__ void k_env1(const float* __restrict__ ang, const int* __restrict__ center)
{
    int idx = blockIdx.x * blockDim.x + threadIdx.x;
    if (idx >= E_NUM * 64) return;
    int e = idx >> 6, u = idx & 63;
    float4 sh = *reinterpret_cast<const float4*>(&ang[e * 4]);
    const float* w = &g_wall[(size_t)e * 192];
    float gate = w[128 + u];
    g_fs1[idx] *= gate;
    g_fv1[idx] *= gate;
    g_fv1[E_NUM * 64 + idx] *= gate;
    g_fv1[2 * E_NUM * 64 + idx] *= gate;
    float we0 = w[2 * u], we1 = w[2 * u + 1];
    int c = center[e];
    atomicAdd(&g_ns[c * 64 + u], we0 * sh.x);
    atomicAdd(&g_nv[c * 64 + u], we1 * sh.y);
    atomicAdd(&g_nv[NN * 64 + c * 64 + u], we1 * sh.z);
    atomicAdd(&g_nv[2 * NN * 64 + c * 64 + u], we1 * sh.w);
}

__global__ void k_nodelin(const float* __restrict__ W)
{
    int nn = blockIdx.x;
    int t = threadIdx.x;
    __shared__ float sin_[256];
    int ch = t >> 6, v = t & 63;
    float val = (ch == 0) ? g_ns[nn * 64 + v] : g_nv[(ch - 1) * NN * 64 + nn * 64 + v];
    sin_[t] = val * 0.05f;
    __syncthreads();
    const float* Wm = W + (ch == 0 ? 0 : 64 * 64);
    float acc = 0.f;
#pragma unroll
    for (int u = 0; u < 64; u++) acc = fmaf(sin_[ch * 64 + u], Wm[u * 64 + v], acc);
    if (ch == 0) g_ns2[nn * 64 + v] = acc;
    else g_nv2[(ch - 1) * NN * 64 + nn * 64 + v] = acc;
}

__global__ void k_tp(const float* __restrict__ fs, const float* __restrict__ fv,
                     const int* __restrict__ center)
{
    int idx = blockIdx.x * blockDim.x + threadIdx.x;
    if (idx >= E_NUM * 64) return;
    int e = idx >> 6, u = idx & 63;
    int c = center[e];
    float s2 = g_ns2[c * 64 + u];
    float vx = g_nv2[c * 64 + u];
    float vy = g_nv2[NN * 64 + c * 64 + u];
    float vz = g_nv2[2 * NN * 64 + c * 64 + u];
    float f = fs[idx];
    float fx = fv[idx];
    float fy = fv[E_NUM * 64 + idx];
    float fz = fv[2 * E_NUM * 64 + idx];
    const float IS3 = 0.57735026918962576f;
    size_t b = (size_t)e * 128 + u;
    g_ts[b] = f * s2;
    g_ts[b + 64] = (fx * vx + fy * vy + fz * vz) * IS3;
    g_tv[b] = f * vx * IS3;
    g_tv[b + 64] = fx * s2 * IS3;
    g_tv[(size_t)E_NUM * 128 + b] = f * vy * IS3;
    g_tv[(size_t)E_NUM * 128 + b + 64] = fy * s2 * IS3;
    g_tv[(size_t)2 * E_NUM * 128 + b] = f * vz * IS3;
    g_tv[(size_t)2 * E_NUM * 128 + b + 64] = fz * s2 * IS3;
}

__global__ void k_prep(const float* __restrict__ sw, const float* __restrict__ vw)
{
    int idx = blockIdx.x * 256 + threadIdx.x;
    if (idx >= 2 * 2 * 64 * 64) return;
    int v = idx & 63;
    int u = (idx >> 6) & 63;
    int o = (idx >> 12) & 1;
    int i = (idx >> 13) & 1;
    int dst = (i * 64 + u) * 128 + o * 64 + v;
    g_sw1[dst] = sw[idx];
    g_vw1[dst] = vw[idx];
}

__global__ void k_out(float* __restrict__ out)
{
    int idx = blockIdx.x * blockDim.x + threadIdx.x;
    if (idx >= E_NUM * 128) return;
    int e = idx >> 7, q = idx & 127;
    out[(size_t)e * 512 + q] = g_fs3[idx] * g_fin[idx];
    float a = g_fv3[idx];
    float b = g_fv3[E_NUM * 128 + idx];
    float c = g_fv3[2 * E_NUM * 128 + idx];
    size_t base = (size_t)e * 512 + 128 + (size_t)q * 3;
    out[base] = a;
    out[base + 1] = b;
    out[base + 2] = c;
}

// ---------------- host launch ----------------
template <typename T>
static float* symaddr(const T& sym)
{
    void* p = nullptr;
    cudaGetSymbolAddress(&p, sym);
    return (float*)p;
}

static const int SMEM128 = (2 * 128 * 36 + 2 * 32 * 136) * 4;
static const int SMEM64 = (2 * 128 * 36 + 2 * 32 * 72) * 4;

extern "C" void kernel_launch(void* const* d_in, const int* in_sizes, int n_in,
                              void* d_out, int out_size)
{
    const float* node_attrs = (const float*)d_in[0];
    const float* radial = (const float*)d_in[1];
    const float* ang = (const float*)d_in[2];
    const float* elen = (const float*)d_in[3];
    const int* eidx = (const int*)d_in[4];
    const float* tb_w0 = (const float*)d_in[5];
    const float* tb_w1 = (const float*)d_in[6];
    const float* tb_w2 = (const float*)d_in[7];
    const float* lat1_w0 = (const float*)d_in[8];
    const float* lat1_w1 = (const float*)d_in[9];
    const float* env0_w = (const float*)d_in[10];
    const float* env1_w = (const float*)d_in[11];
    const float* envlin0 = (const float*)d_in[12];
    const float* envlin1 = (const float*)d_in[13];
    const float* lin0_sw = (const float*)d_in[14];
    const float* lin0_vw = (const float*)d_in[15];
    const float* lin1_sw = (const float*)d_in[16];
    const float* lin1_vw = (const float*)d_in[17];
    const float* fin_w0 = (const float*)d_in[18];
    const float* fin_w1 = (const float*)d_in[19];
    const float* res_p = (const float*)d_in[20];
    float* out = (float*)d_out;

    float* An = symaddr(g_An);
    float* Bn = symaddr(g_Bn);
    float* cut = symaddr(g_cut);
    float* h0 = symaddr(g_h0);
    float* h1 = symaddr(g_h1);
    float* lat = symaddr(g_lat);
    float* wall = symaddr(g_wall);
    float* fs = symaddr(g_fs);
    float* fv = symaddr(g_fv);
    float* fs1 = symaddr(g_fs1);
    float* fv1 = symaddr(g_fv1);
    float* ts = symaddr(g_ts);
    float* tv = symaddr(g_tv);
    float* fs3 = symaddr(g_fs3);
    float* fv3 = symaddr(g_fv3);
    float* fin = symaddr(g_fin);
    float* sw1 = symaddr(g_sw1);
    float* vw1 = symaddr(g_vw1);

    (void)in_sizes; (void)n_in; (void)out_size;

    cudaFuncSetAttribute(gemm_tc<128, 0>, cudaFuncAttributeMaxDynamicSharedMemorySize, SMEM128);
    cudaFuncSetAttribute(gemm_tc<128, 1>, cudaFuncAttributeMaxDynamicSharedMemorySize, SMEM128);
    cudaFuncSetAttribute(gemm_tc<128, 2>, cudaFuncAttributeMaxDynamicSharedMemorySize, SMEM128);
    cudaFuncSetAttribute(gemm_tc<128, 3>, cudaFuncAttributeMaxDynamicSharedMemorySize, SMEM128);
    cudaFuncSetAttribute(gemm_tc<64, 0>, cudaFuncAttributeMaxDynamicSharedMemorySize, SMEM64);

    auto g128 = [](int M, int N) { return dim3((M + 127) / 128, N / 128); };
    auto g64 = [](int M, int N) { return dim3((M + 127) / 128, N / 64); };
    const int EW = (E_NUM * 64 + 255) / 256;
    const int ZB = (NN * 64 + 255) / 256;
    const int E64c = E_NUM * 64;
    const int E128c = E_NUM * 128;

    // node precompute
    gemm_tc<128, 0><<<g128(NN, 256), 256, SMEM128>>>(node_attrs, 64, nullptr, 0, tb_w0, An, NN, 256, nullptr, nullptr);
    gemm_tc<128, 0><<<g128(NN, 256), 256, SMEM128>>>(node_attrs, 64, nullptr, 0, tb_w0 + 64 * 256, Bn, NN, 256, nullptr, nullptr);

    // first layer + cut
    k_first<<<E_NUM, 256>>>(radial, elen, eidx, tb_w0 + 128 * 256);

    // tb MLP
    gemm_tc<128, 1><<<g128(E_NUM, 256), 256, SMEM128>>>(h0, 256, nullptr, 0, tb_w1, h1, E_NUM, 256, nullptr, nullptr);
    gemm_tc<128, 2><<<g128(E_NUM, 256), 256, SMEM128>>>(h1, 256, nullptr, 0, tb_w2, lat, E_NUM, 256, cut, nullptr);

    // env0
    gemm_tc<64, 0><<<g64(E_NUM, 320), 256, SMEM64>>>(lat, 256, nullptr, 0, env0_w, wall, E_NUM, 320, nullptr, nullptr);
    k_zero<<<ZB, 256>>>();
    k_env0<<<EW, 256>>>(ang, eidx);
    k_nodelin<<<NN, 256>>>(envlin0);
    k_tp<<<EW, 256>>>(fs, fv, eidx);

    // lin0
    gemm_tc<64, 0><<<g64(E_NUM, 64), 256, SMEM64>>>(ts, 128, nullptr, 0, lin0_sw, fs1, E_NUM, 64, nullptr, nullptr);
    for (int c = 0; c < 3; c++)
        gemm_tc<64, 0><<<g64(E_NUM, 64), 256, SMEM64>>>(tv + (size_t)c * E128c, 128, nullptr, 0, lin0_vw,
                                                        fv1 + (size_t)c * E64c, E_NUM, 64, nullptr, nullptr);

    // lat1 MLP + residual
    gemm_tc<128, 1><<<g128(E_NUM, 256), 256, SMEM128>>>(lat, 256, ts, 128, lat1_w0, h1, E_NUM, 256, nullptr, nullptr);
    gemm_tc<128, 3><<<g128(E_NUM, 256), 256, SMEM128>>>(h1, 256, nullptr, 0, lat1_w1, lat, E_NUM, 256, cut, res_p);

    // env1
    gemm_tc<64, 0><<<g64(E_NUM, 192), 256, SMEM64>>>(lat, 256, nullptr, 0, env1_w, wall, E_NUM, 192, nullptr, nullptr);
    k_zero<<<ZB, 256>>>();
    k_env1<<<EW, 256>>>(ang, eidx);
    k_nodelin<<<NN, 256>>>(envlin1);
    k_tp<<<EW, 256>>>(fs1, fv1, eidx);

    // lin1
    k_prep<<<(2 * 2 * 64 * 64 + 255) / 256, 256>>>(lin1_sw, lin1_vw);
    gemm_tc<128, 0><<<g128(E_NUM, 128), 256, SMEM128>>>(ts, 128, nullptr, 0, sw1, fs3, E_NUM, 128, nullptr, nullptr);
    for (int c = 0; c < 3; c++)
        gemm_tc<128, 0><<<g128(E_NUM, 128), 256, SMEM128>>>(tv + (size_t)c * E128c, 128, nullptr, 0, vw1,
                                                            fv3 + (size_t)c * E128c, E_NUM, 128, nullptr, nullptr);

    // fin MLP
    gemm_tc<128, 1><<<g128(E_NUM, 256), 256, SMEM128>>>(lat, 256, ts, 128, fin_w0, h1, E_NUM, 256, nullptr, nullptr);
    gemm_tc<128, 0><<<g128(E_NUM, 128), 256, SMEM128>>>(h1, 256, nullptr, 0, fin_w1, fin, E_NUM, 128, nullptr, nullptr);

    // output
    k_out<<<(E_NUM * 128 + 255) / 256, 256>>>(out);
}

// round 4
// speedup vs baseline: 1.3700x; 1.0375x over previous
#include <cuda_runtime.h>
#include <math.h>

#define E_NUM 100000
#define NN 5000

// ---------------- device scratch ----------------
__device__ __align__(16) float g_An[NN * 256];
__device__ __align__(16) float g_Bn[NN * 256];
__device__ __align__(16) float g_cut[E_NUM];
__device__ __align__(16) float g_h0[E_NUM * 256];
__device__ __align__(16) float g_h1[E_NUM * 256];
__device__ __align__(16) float g_lat[E_NUM * 256];
__device__ __align__(16) float g_wall[E_NUM * 320];
__device__ __align__(16) float g_fs1[E_NUM * 64];
__device__ __align__(16) float g_fv1[3 * E_NUM * 64];
__device__ __align__(16) float g_ns[NN * 64];
__device__ __align__(16) float g_nv[3 * NN * 64];
__device__ __align__(16) float g_ns2[NN * 64];
__device__ __align__(16) float g_nv2[3 * NN * 64];
__device__ __align__(16) float g_ts[E_NUM * 128];
__device__ __align__(16) float g_tv[3 * E_NUM * 128];
__device__ __align__(16) float g_fs3[E_NUM * 128];
__device__ __align__(16) float g_sw1[128 * 128];
__device__ __align__(16) float g_vw1[128 * 128];

__device__ __forceinline__ float siluf(float x) { return x / (1.0f + expf(-x)); }

__device__ __forceinline__ unsigned f2tf(float x)
{
    unsigned r;
    asm("cvt.rna.tf32.f32 %0, %1;" : "=r"(r) : "f"(x));
    return r;
}
__device__ __forceinline__ void tfsplit(float x, unsigned& hi, unsigned& lo)
{
    hi = f2tf(x);
    lo = f2tf(x - __uint_as_float(hi));
}
__device__ __forceinline__ void cp16(unsigned d, const void* s, int sz)
{
    asm volatile("cp.async.cg.shared.global [%0], [%1], 16, %2;\n" :: "r"(d), "l"(s), "r"(sz));
}
__device__ __forceinline__ void cp_commit() { asm volatile("cp.async.commit_group;\n"); }
__device__ __forceinline__ void cp_wait1() { asm volatile("cp.async.wait_group 1;\n"); }

#define MMA_TF32(ACC, A0, A1, A2, A3, B0, B1)                                     \
    asm volatile(                                                                 \
        "mma.sync.aligned.m16n8k8.row.col.f32.tf32.tf32.f32 "                     \
        "{%0,%1,%2,%3},{%4,%5,%6,%7},{%8,%9},{%0,%1,%2,%3};"                      \
        : "+f"((ACC)[0]), "+f"((ACC)[1]), "+f"((ACC)[2]), "+f"((ACC)[3])          \
        : "r"(A0), "r"(A1), "r"(A2), "r"(A3), "r"(B0), "r"(B1))

// ============ 3xTF32 GEMM, 128x64 tile, 2 CTA/SM =============
// EPI: 0 none, 1 silu, 2 cut[m]*acc, 3 residual C=c1*C+c2*cut*acc,
//      4 out[row*512+col] = acc * aux[row*128+col],
//      5 out[row*512+128+col*3+comp] = acc
template <int EPI>
__global__ void __launch_bounds__(256, 2) gemm_tc(
    const float* __restrict__ A1, int K1,
    const float* __restrict__ A2, int K2,
    const float* __restrict__ B, float* __restrict__ C,
    int M, int N,
    const float* __restrict__ caux, const float* __restrict__ res_p, int comp)
{
    constexpr int BM = 128, BK = 32, BN = 64;
    constexpr int WM = 32, WN = 32, MT = 2, NT = 4;
    constexpr int ASTR = 36, BSTR = 72;

    extern __shared__ float sm[];
    float* As = sm;                  // [2][BM][ASTR]
    float* Bs = sm + 2 * BM * ASTR;  // [2][BK][BSTR]
    unsigned asb = (unsigned)__cvta_generic_to_shared(As);
    unsigned bsb = (unsigned)__cvta_generic_to_shared(Bs);

    const int tid = threadIdx.x;
    const int lane = tid & 31;
    const int warp = tid >> 5;
    const int g = lane >> 2;
    const int kq = lane & 3;
    const int wm = warp & 3;
    const int wn = warp >> 2;
    const int m0 = blockIdx.x * BM;
    const int n0 = blockIdx.y * BN;
    const int K = K1 + K2;
    const int T = K / BK;

    float acc[MT][NT][4];
#pragma unroll
    for (int i = 0; i < MT; i++)
#pragma unroll
        for (int j = 0; j < NT; j++)
#pragma unroll
            for (int q = 0; q < 4; q++) acc[i][j][q] = 0.0f;

    auto loadA = [&](int kt, int buf) {
        int k0 = kt * BK;
        const float* A; int lda, kl;
        if (k0 < K1) { A = A1; lda = K1; kl = k0; }
        else { A = A2; lda = K2; kl = k0 - K1; }
        int c = (tid & 7) * 4;
        int mb = tid >> 3;
#pragma unroll
        for (int p = 0; p < 4; p++) {
            int m = mb + p * 32;
            int gm = m0 + m;
            unsigned dst = asb + (unsigned)(((buf * BM + m) * ASTR + c) * 4);
            const float* src = A + (size_t)gm * lda + kl + c;
            cp16(dst, src, (gm < M) ? 16 : 0);
        }
    };
    auto loadB = [&](int kt, int buf) {
        int k0 = kt * BK;
        int c = (tid & 15) * 4;
        int rb = tid >> 4;
#pragma unroll
        for (int p = 0; p < 2; p++) {
            int r = rb + p * 16;
            unsigned dst = bsb + (unsigned)(((buf * BK + r) * BSTR + c) * 4);
            const float* src = B + (size_t)(k0 + r) * N + n0 + c;
            cp16(dst, src, 16);
        }
    };
    auto compute = [&](int buf) {
#pragma unroll
        for (int ks = 0; ks < BK / 8; ks++) {
            unsigned ah[MT][4], al[MT][4], bh[NT][2], bl[NT][2];
#pragma unroll
            for (int mt = 0; mt < MT; mt++) {
                int r = wm * WM + mt * 16 + g;
                const float* ap = &As[(buf * BM + r) * ASTR + ks * 8 + kq];
                tfsplit(ap[0], ah[mt][0], al[mt][0]);
                tfsplit(ap[8 * ASTR], ah[mt][1], al[mt][1]);
                tfsplit(ap[4], ah[mt][2], al[mt][2]);
                tfsplit(ap[8 * ASTR + 4], ah[mt][3], al[mt][3]);
            }
#pragma unroll
            for (int nt = 0; nt < NT; nt++) {
                int n = wn * WN + nt * 8 + g;
                const float* bp = &Bs[(buf * BK + ks * 8 + kq) * BSTR + n];
                tfsplit(bp[0], bh[nt][0], bl[nt][0]);
                tfsplit(bp[4 * BSTR], bh[nt][1], bl[nt][1]);
            }
#pragma unroll
            for (int mt = 0; mt < MT; mt++)
#pragma unroll
                for (int nt = 0; nt < NT; nt++) {
                    MMA_TF32(acc[mt][nt], al[mt][0], al[mt][1], al[mt][2], al[mt][3],
                             bh[nt][0], bh[nt][1]);
                    MMA_TF32(acc[mt][nt], ah[mt][0], ah[mt][1], ah[mt][2], ah[mt][3],
                             bl[nt][0], bl[nt][1]);
                    MMA_TF32(acc[mt][nt], ah[mt][0], ah[mt][1], ah[mt][2], ah[mt][3],
                             bh[nt][0], bh[nt][1]);
                }
        }
    };

    loadA(0, 0); loadB(0, 0); cp_commit();
    for (int t = 0; t < T; t++) {
        if (t + 1 < T) { loadA(t + 1, (t + 1) & 1); loadB(t + 1, (t + 1) & 1); }
        cp_commit();
        cp_wait1();
        __syncthreads();
        compute(t & 1);
        __syncthreads();
    }

    float rc1 = 0.f, rc2 = 0.f;
    if (EPI == 3) {
        float av = 1.0f / (1.0f + expf(-res_p[1]));
        rc1 = sqrtf(1.0f - av);
        rc2 = sqrtf(av);
    }
#pragma unroll
    for (int mt = 0; mt < MT; mt++) {
#pragma unroll
        for (int h = 0; h < 2; h++) {
            int row = m0 + wm * WM + mt * 16 + g + h * 8;
            if (row >= M) continue;
            float rs = (EPI == 2 || EPI == 3) ? caux[row] : 0.0f;
#pragma unroll
            for (int nt = 0; nt < NT; nt++) {
                int col = n0 + wn * WN + nt * 8 + kq * 2;
                float v0 = acc[mt][nt][2 * h];
                float v1 = acc[mt][nt][2 * h + 1];
                if (EPI == 1) { v0 = siluf(v0); v1 = siluf(v1); }
                else if (EPI == 2) { v0 *= rs; v1 *= rs; }
                else if (EPI == 3) {
                    float2 o = *reinterpret_cast<const float2*>(&C[(size_t)row * N + col]);
                    v0 = rc1 * o.x + rc2 * rs * v0;
                    v1 = rc1 * o.y + rc2 * rs * v1;
                }
                if (EPI == 4) {
                    float s0 = caux[(size_t)row * 128 + col];
                    float s1 = caux[(size_t)row * 128 + col + 1];
                    float2 w = make_float2(v0 * s0, v1 * s1);
                    *reinterpret_cast<float2*>(&C[(size_t)row * 512 + col]) = w;
                } else if (EPI == 5) {
                    size_t b = (size_t)row * 512 + 128 + (size_t)col * 3 + comp;
                    C[b] = v0;
                    C[b + 3] = v1;
                } else {
                    float2 w = make_float2(v0, v1);
                    *reinterpret_cast<float2*>(&C[(size_t)row * N + col]) = w;
                }
            }
        }
    }
}

// ---------------- first layer ----------------
__global__ void k_first(const float* __restrict__ radial, const float* __restrict__ elen,
                        const int* __restrict__ eidx, const float* __restrict__ w0r)
{
    int e = blockIdx.x;
    int t = threadIdx.x;
    __shared__ float r[8];
    if (t < 8) r[t] = radial[e * 8 + t];
    if (t == 0) {
        float x = elen[e] * 0.2f;
        float x2 = x * x;
        float x6 = x2 * x2 * x2;
        float o = 1.0f - 28.0f * x6 + 48.0f * x6 * x - 21.0f * x6 * x2;
        g_cut[e] = (x < 1.0f) ? o : 0.0f;
    }
    __syncthreads();
    int c = eidx[e];
    int n = eidx[E_NUM + e];
    float acc = g_An[c * 256 + t] + g_Bn[n * 256 + t];
#pragma unroll
    for (int j = 0; j < 8; j++) acc = fmaf(r[j], w0r[j * 256 + t], acc);
    g_h0[(size_t)e * 256 + t] = siluf(acc);
}

__global__ void k_zero()
{
    int i = blockIdx.x * 256 + threadIdx.x;
    if (i < NN * 64) {
        g_ns[i] = 0.f;
        g_nv[i] = 0.f;
        g_nv[NN * 64 + i] = 0.f;
        g_nv[2 * NN * 64 + i] = 0.f;
    }
}

// ---------------- scatter: atomics from w_env slice of wall ----------------
__global__ void k_scatter(const float* __restrict__ ang, const int* __restrict__ center, int S)
{
    int idx = blockIdx.x * blockDim.x + threadIdx.x;
    if (idx >= E_NUM * 64) return;
    int e = idx >> 6, u = idx & 63;
    float4 sh = *reinterpret_cast<const float4*>(&ang[e * 4]);
    const float* w = &g_wall[(size_t)e * S];
    float we0 = w[2 * u], we1 = w[2 * u + 1];
    int c = center[e];
    atomicAdd(&g_ns[c * 64 + u], we0 * sh.x);
    atomicAdd(&g_nv[c * 64 + u], we1 * sh.y);
    atomicAdd(&g_nv[NN * 64 + c * 64 + u], we1 * sh.z);
    atomicAdd(&g_nv[2 * NN * 64 + c * 64 + u], we1 * sh.w);
}

__global__ void k_nodelin(const float* __restrict__ W)
{
    int nn = blockIdx.x;
    int t = threadIdx.x;
    __shared__ float sin_[256];
    int ch = t >> 6, v = t & 63;
    float val = (ch == 0) ? g_ns[nn * 64 + v] : g_nv[(ch - 1) * NN * 64 + nn * 64 + v];
    sin_[t] = val * 0.05f;
    __syncthreads();
    const float* Wm = W + (ch == 0 ? 0 : 64 * 64);
    float acc = 0.f;
#pragma unroll
    for (int u = 0; u < 64; u++) acc = fmaf(sin_[ch * 64 + u], Wm[u * 64 + v], acc);
    if (ch == 0) g_ns2[nn * 64 + v] = acc;
    else g_nv2[(ch - 1) * NN * 64 + nn * 64 + v] = acc;
}

// ---------------- common TP tail ----------------
__device__ __forceinline__ void tp_tail(int e, int u, int c,
                                        float f, float fx, float fy, float fz)
{
    float s2 = g_ns2[c * 64 + u];
    float vx = g_nv2[c * 64 + u];
    float vy = g_nv2[NN * 64 + c * 64 + u];
    float vz = g_nv2[2 * NN * 64 + c * 64 + u];
    const float IS3 = 0.57735026918962576f;
    size_t b = (size_t)e * 128 + u;
    g_ts[b] = f * s2;
    g_ts[b + 64] = (fx * vx + fy * vy + fz * vz) * IS3;
    g_tv[b] = f * vx * IS3;
    g_tv[b + 64] = fx * s2 * IS3;
    g_tv[(size_t)E_NUM * 128 + b] = f * vy * IS3;
    g_tv[(size_t)E_NUM * 128 + b + 64] = fy * s2 * IS3;
    g_tv[(size_t)2 * E_NUM * 128 + b] = f * vz * IS3;
    g_tv[(size_t)2 * E_NUM * 128 + b + 64] = fz * s2 * IS3;
}

// stage0: fs/fv computed in-flight from wall (S=320)
__global__ void k_tp0(const float* __restrict__ ang, const int* __restrict__ center)
{
    int idx = blockIdx.x * blockDim.x + threadIdx.x;
    if (idx >= E_NUM * 64) return;
    int e = idx >> 6, u = idx & 63;
    float4 sh = *reinterpret_cast<const float4*>(&ang[e * 4]);
    const float* w = &g_wall[(size_t)e * 320];
    float gate = w[128 + u];
    float wf0 = w[192 + 2 * u], wf1 = w[193 + 2 * u];
    float f = wf0 * sh.x * gate;
    float fx = wf1 * sh.y * gate;
    float fy = wf1 * sh.z * gate;
    float fz = wf1 * sh.w * gate;
    tp_tail(e, u, center[e], f, fx, fy, fz);
}

// stage1: gate (from wall S=192) folded in here, fs1/fv1 read-only
__global__ void k_tp1(const float* __restrict__ ang, const int* __restrict__ center)
{
    int idx = blockIdx.x * blockDim.x + threadIdx.x;
    if (idx >= E_NUM * 64) return;
    int e = idx >> 6, u = idx & 63;
    float gate = g_wall[(size_t)e * 192 + 128 + u];
    float f = g_fs1[idx] * gate;
    float fx = g_fv1[idx] * gate;
    float fy = g_fv1[E_NUM * 64 + idx] * gate;
    float fz = g_fv1[2 * E_NUM * 64 + idx] * gate;
    tp_tail(e, u, center[e], f, fx, fy, fz);
}

__global__ void k_prep(const float* __restrict__ sw, const float* __restrict__ vw)
{
    int idx = blockIdx.x * 256 + threadIdx.x;
    if (idx >= 2 * 2 * 64 * 64) return;
    int v = idx & 63;
    int u = (idx >> 6) & 63;
    int o = (idx >> 12) & 1;
    int i = (idx >> 13) & 1;
    int dst = (i * 64 + u) * 128 + o * 64 + v;
    g_sw1[dst] = sw[idx];
    g_vw1[dst] = vw[idx];
}

// ---------------- host launch ----------------
template <typename T>
static float* symaddr(const T& sym)
{
    void* p = nullptr;
    cudaGetSymbolAddress(&p, sym);
    return (float*)p;
}

static const int SMEM = (2 * 128 * 36 + 2 * 32 * 72) * 4;  // 55296

extern "C" void kernel_launch(void* const* d_in, const int* in_sizes, int n_in,
                              void* d_out, int out_size)
{
    const float* node_attrs = (const float*)d_in[0];
    const float* radial = (const float*)d_in[1];
    const float* ang = (const float*)d_in[2];
    const float* elen = (const float*)d_in[3];
    const int* eidx = (const int*)d_in[4];
    const float* tb_w0 = (const float*)d_in[5];
    const float* tb_w1 = (const float*)d_in[6];
    const float* tb_w2 = (const float*)d_in[7];
    const float* lat1_w0 = (const float*)d_in[8];
    const float* lat1_w1 = (const float*)d_in[9];
    const float* env0_w = (const float*)d_in[10];
    const float* env1_w = (const float*)d_in[11];
    const float* envlin0 = (const float*)d_in[12];
    const float* envlin1 = (const float*)d_in[13];
    const float* lin0_sw = (const float*)d_in[14];
    const float* lin0_vw = (const float*)d_in[15];
    const float* lin1_sw = (const float*)d_in[16];
    const float* lin1_vw = (const float*)d_in[17];
    const float* fin_w0 = (const float*)d_in[18];
    const float* fin_w1 = (const float*)d_in[19];
    const float* res_p = (const float*)d_in[20];
    float* out = (float*)d_out;

    float* An = symaddr(g_An);
    float* Bn = symaddr(g_Bn);
    float* cut = symaddr(g_cut);
    float* h0 = symaddr(g_h0);
    float* h1 = symaddr(g_h1);
    float* lat = symaddr(g_lat);
    float* wall = symaddr(g_wall);
    float* fs1 = symaddr(g_fs1);
    float* fv1 = symaddr(g_fv1);
    float* ts = symaddr(g_ts);
    float* tv = symaddr(g_tv);
    float* fs3 = symaddr(g_fs3);
    float* sw1 = symaddr(g_sw1);
    float* vw1 = symaddr(g_vw1);

    (void)in_sizes; (void)n_in; (void)out_size;

    cudaFuncSetAttribute(gemm_tc<0>, cudaFuncAttributeMaxDynamicSharedMemorySize, SMEM);
    cudaFuncSetAttribute(gemm_tc<1>, cudaFuncAttributeMaxDynamicSharedMemorySize, SMEM);
    cudaFuncSetAttribute(gemm_tc<2>, cudaFuncAttributeMaxDynamicSharedMemorySize, SMEM);
    cudaFuncSetAttribute(gemm_tc<3>, cudaFuncAttributeMaxDynamicSharedMemorySize, SMEM);
    cudaFuncSetAttribute(gemm_tc<4>, cudaFuncAttributeMaxDynamicSharedMemorySize, SMEM);
    cudaFuncSetAttribute(gemm_tc<5>, cudaFuncAttributeMaxDynamicSharedMemorySize, SMEM);

    auto g64 = [](int M, int N) { return dim3((M + 127) / 128, N / 64); };
    const int EW = (E_NUM * 64 + 255) / 256;
    const int ZB = (NN * 64 + 255) / 256;
    const int E64c = E_NUM * 64;
    const int E128c = E_NUM * 128;

    // node precompute
    gemm_tc<0><<<g64(NN, 256), 256, SMEM>>>(node_attrs, 64, nullptr, 0, tb_w0, An, NN, 256, nullptr, nullptr, 0);
    gemm_tc<0><<<g64(NN, 256), 256, SMEM>>>(node_attrs, 64, nullptr, 0, tb_w0 + 64 * 256, Bn, NN, 256, nullptr, nullptr, 0);

    // first layer + cut
    k_first<<<E_NUM, 256>>>(radial, elen, eidx, tb_w0 + 128 * 256);

    // tb MLP
    gemm_tc<1><<<g64(E_NUM, 256), 256, SMEM>>>(h0, 256, nullptr, 0, tb_w1, h1, E_NUM, 256, nullptr, nullptr, 0);
    gemm_tc<2><<<g64(E_NUM, 256), 256, SMEM>>>(h1, 256, nullptr, 0, tb_w2, lat, E_NUM, 256, cut, nullptr, 0);

    // env0
    gemm_tc<0><<<g64(E_NUM, 320), 256, SMEM>>>(lat, 256, nullptr, 0, env0_w, wall, E_NUM, 320, nullptr, nullptr, 0);
    k_zero<<<ZB, 256>>>();
    k_scatter<<<EW, 256>>>(ang, eidx, 320);
    k_nodelin<<<NN, 256>>>(envlin0);
    k_tp0<<<EW, 256>>>(ang, eidx);

    // lin0
    gemm_tc<0><<<g64(E_NUM, 64), 256, SMEM>>>(ts, 128, nullptr, 0, lin0_sw, fs1, E_NUM, 64, nullptr, nullptr, 0);
    for (int c = 0; c < 3; c++)
        gemm_tc<0><<<g64(E_NUM, 64), 256, SMEM>>>(tv + (size_t)c * E128c, 128, nullptr, 0, lin0_vw,
                                                  fv1 + (size_t)c * E64c, E_NUM, 64, nullptr, nullptr, 0);

    // lat1 MLP + residual
    gemm_tc<1><<<g64(E_NUM, 256), 256, SMEM>>>(lat, 256, ts, 128, lat1_w0, h1, E_NUM, 256, nullptr, nullptr, 0);
    gemm_tc<3><<<g64(E_NUM, 256), 256, SMEM>>>(h1, 256, nullptr, 0, lat1_w1, lat, E_NUM, 256, cut, res_p, 0);

    // env1
    gemm_tc<0><<<g64(E_NUM, 192), 256, SMEM>>>(lat, 256, nullptr, 0, env1_w, wall, E_NUM, 192, nullptr, nullptr, 0);
    k_zero<<<ZB, 256>>>();
    k_scatter<<<EW, 256>>>(ang, eidx, 192);
    k_nodelin<<<NN, 256>>>(envlin1);
    k_tp1<<<EW, 256>>>(ang, eidx);

    // lin1: sw -> fs3; vw -> out directly (vector half)
    k_prep<<<(2 * 2 * 64 * 64 + 255) / 256, 256>>>(lin1_sw, lin1_vw);
    gemm_tc<0><<<g64(E_NUM, 128), 256, SMEM>>>(ts, 128, nullptr, 0, sw1, fs3, E_NUM, 128, nullptr, nullptr, 0);
    for (int c = 0; c < 3; c++)
        gemm_tc<5><<<g64(E_NUM, 128), 256, SMEM>>>(tv + (size_t)c * E128c, 128, nullptr, 0, vw1,
                                                   out, E_NUM, 128, nullptr, nullptr, c);

    // fin MLP: second layer fused with fs3 multiply, writes scalar half of out
    gemm_tc<1><<<g64(E_NUM, 256), 256, SMEM>>>(lat, 256, ts, 128, fin_w0, h1, E_NUM, 256, nullptr, nullptr, 0);
    gemm_tc<4><<<g64(E_NUM, 128), 256, SMEM>>>(h1, 256, nullptr, 0, fin_w1, out, E_NUM, 128, fs3, nullptr, 0);
}